// round 9
// baseline (speedup 1.0000x reference)
#include <cuda_runtime.h>
#include <cstdint>

#define N_NODES 100000
#define DIM 16
#define NF   (N_NODES * DIM)       // total floats in node matrix
#define N4   (NF / 4)              // float4 count

// Edge-message accumulator. Zero-initialized at module load; the finalize
// kernel re-zeros it every call, so each graph replay starts from zero.
__device__ float4 g_acc[N4];

// ---------------------------------------------------------------------------
// Kernel 1: scatter, 4 threads per edge (thread = one 16B chunk of the row).
// Index-dtype detection is PER-WARP and barrier-free: each warp reads the
// first 64 8-byte words of edge_index (2 broadcast loads/lane, L1-hot after
// the first warp) and ballots. If the buffer is int32, the high words are
// random node ids -> almost surely outside [0, N_NODES); all-in-range <=>
// genuinely int64.
// Lanes 4k..4k+3 read consecutive 16B of x[src] -> a warp's gather touches
// 8 random rows (1 wavefront/edge) instead of 32. One red.global.add.v4.f32
// per thread (no-return 128b L2 reduction). The kernel sits on the REDG
// per-lane issue floor (~12.8M lane-ops) — algorithmically minimal.
// ---------------------------------------------------------------------------
__global__ void __launch_bounds__(512)
ldl_scatter_kernel(const float4* __restrict__ x,
                   const void* __restrict__ eidx,
                   const float* __restrict__ probs,
                   const float* __restrict__ weight,
                   int E) {
    // --- per-warp dtype detect (no syncthreads, no smem) ---
    int lane = threadIdx.x & 31;
    unsigned long long v0 = ((const unsigned long long*)eidx)[lane];
    unsigned long long v1 = ((const unsigned long long*)eidx)[32 + lane];
    bool okl = (v0 < (unsigned long long)N_NODES) &&
               (v1 < (unsigned long long)N_NODES);
    bool is64 = (__ballot_sync(0xFFFFFFFFu, okl) == 0xFFFFFFFFu);

    int t = blockIdx.x * blockDim.x + threadIdx.x;
    int e = t >> 2;
    int c = t & 3;
    if (e >= E) return;

    unsigned long long s, d;
    if (is64) {
        const unsigned long long* p = (const unsigned long long*)eidx;
        s = __ldg(p + e);
        d = __ldg(p + E + e);
    } else {
        const unsigned int* p = (const unsigned int*)eidx;
        s = __ldg(p + e);
        d = __ldg(p + E + e);
    }
    // Backstop (unsigned compare folds the negative check).
    if (s >= N_NODES || d >= N_NODES) return;

    float pr = __ldg(probs + e);
    float4 wv = __ldg((const float4*)weight + c);   // warp-broadcast L1 hit
    float4 xv = __ldg(x + s * 4 + c);

    float a0 = xv.x * pr * wv.x;
    float a1 = xv.y * pr * wv.y;
    float a2 = xv.z * pr * wv.z;
    float a3 = xv.w * pr * wv.w;
    float* op = (float*)g_acc + d * DIM + c * 4;
    asm volatile(
        "red.global.add.v4.f32 [%0], {%1, %2, %3, %4};"
        :: "l"(op), "f"(a0), "f"(a1), "f"(a2), "f"(a3)
        : "memory");
}

// ---------------------------------------------------------------------------
// Kernel 2: finalize. out = clip(x*(1+slw) + acc, 0, 1), and re-zero acc so
// the next graph replay starts clean. 25.6 MB total traffic, one wave.
// ---------------------------------------------------------------------------
__global__ void __launch_bounds__(256)
ldl_final_kernel(const float4* __restrict__ x,
                 const float* __restrict__ slw,
                 float4* __restrict__ out) {
    int i = blockIdx.x * blockDim.x + threadIdx.x;
    if (i < N4) {
        float s = 1.0f + __ldg(slw);
        float4 xv = x[i];
        float4 av = g_acc[i];
        float4 v;
        v.x = fminf(fmaxf(fmaf(xv.x, s, av.x), 0.0f), 1.0f);
        v.y = fminf(fmaxf(fmaf(xv.y, s, av.y), 0.0f), 1.0f);
        v.z = fminf(fmaxf(fmaf(xv.z, s, av.z), 0.0f), 1.0f);
        v.w = fminf(fmaxf(fmaf(xv.w, s, av.w), 0.0f), 1.0f);
        out[i] = v;
        g_acc[i] = make_float4(0.0f, 0.0f, 0.0f, 0.0f);
    }
}

// ---------------------------------------------------------------------------
// Launch. Inputs (metadata order):
//   d_in[0] x                [N_NODES, 16] float32
//   d_in[1] edge_index       [2, E]        int64 OR int32 (runtime-detected)
//   d_in[2] edge_probs       [E]           float32
//   d_in[3] weight           [16]          float32
//   d_in[4] self_loop_weight scalar        float32
// Graph: [scatter -> finalize]; accumulator scratch keeps init off the
// critical path.
// ---------------------------------------------------------------------------
extern "C" void kernel_launch(void* const* d_in, const int* in_sizes, int n_in,
                              void* d_out, int out_size) {
    const float4* x     = (const float4*)d_in[0];
    const void*   eidx  = d_in[1];
    const float*  probs = (const float*)d_in[2];
    const float*  w     = (const float*)d_in[3];
    const float*  slw   = (const float*)d_in[4];
    float*        out   = (float*)d_out;

    const int E = in_sizes[2];   // edge_probs element count

    long long n = 4LL * E;
    int gScat = (int)((n + 511) / 512);
    ldl_scatter_kernel<<<gScat, 512>>>(x, eidx, probs, w, E);

    int gFin = (N4 + 255) / 256;
    ldl_final_kernel<<<gFin, 256>>>(x, slw, (float4*)out);
}

// round 10
// speedup vs baseline: 1.0328x; 1.0328x over previous
#include <cuda_runtime.h>
#include <cstdint>

#define N_NODES 100000
#define DIM 16
#define NF   (N_NODES * DIM)       // total floats in node matrix
#define N4   (NF / 4)              // float4 count

// Edge-message accumulator. Zero-initialized at module load; the finalize
// kernel re-zeros it every call, so each graph replay starts from zero.
__device__ float4 g_acc[N4];

// ---------------------------------------------------------------------------
// Kernel 1: scatter — EXACT R7 configuration (measured best: 54.8us).
// 4 threads per edge (thread = one 16B chunk of the row). Per-block dtype
// detect: threads 0..63 read the first 64 8-byte words of edge_index; if the
// buffer is int32, high words are random node ids -> almost surely outside
// [0, N_NODES); all-in-range <=> int64. One __syncthreads per block (cheap at
// T=256; the per-warp variant measured WORSE in R9).
// Lanes 4k..4k+3 read consecutive 16B of x[src] -> warp gather touches 8
// random rows instead of 32. One red.global.add.v4.f32 per thread (no-return
// 128b L2 reduction). Sits on the REDG per-lane issue floor.
// ---------------------------------------------------------------------------
__global__ void __launch_bounds__(256)
ldl_scatter_kernel(const float4* __restrict__ x,
                   const void* __restrict__ eidx,
                   const float* __restrict__ probs,
                   const float* __restrict__ weight,
                   int E) {
    __shared__ int s_ok[2];
    {
        int tid = threadIdx.x;
        if (tid < 64) {
            long long v = ((const long long*)eidx)[tid];
            bool ok = (v >= 0 && v < N_NODES);
            unsigned b = __ballot_sync(0xFFFFFFFFu, ok);
            if ((tid & 31) == 0) s_ok[tid >> 5] = (b == 0xFFFFFFFFu);
        }
        __syncthreads();
    }
    bool is64 = (s_ok[0] && s_ok[1]);

    int t = blockIdx.x * blockDim.x + threadIdx.x;
    int e = t >> 2;
    int c = t & 3;
    if (e >= E) return;

    long long s, d;
    if (is64) {
        const long long* p = (const long long*)eidx;
        s = __ldg(p + e);
        d = __ldg(p + E + e);
    } else {
        const int* p = (const int*)eidx;
        s = __ldg(p + e);
        d = __ldg(p + E + e);
    }
    if (s < 0 || s >= N_NODES || d < 0 || d >= N_NODES) return;  // backstop

    float pr = __ldg(probs + e);
    float4 wv = __ldg((const float4*)weight + c);   // warp-broadcast L1 hit
    float4 xv = __ldg(x + s * 4 + c);

    float a0 = xv.x * pr * wv.x;
    float a1 = xv.y * pr * wv.y;
    float a2 = xv.z * pr * wv.z;
    float a3 = xv.w * pr * wv.w;
    float* op = (float*)g_acc + d * DIM + c * 4;
    asm volatile(
        "red.global.add.v4.f32 [%0], {%1, %2, %3, %4};"
        :: "l"(op), "f"(a0), "f"(a1), "f"(a2), "f"(a3)
        : "memory");
}

// ---------------------------------------------------------------------------
// Kernel 2: finalize. out = clip(x*(1+slw) + acc, 0, 1) and re-zero acc.
// 2 float4 per thread, all 4 loads issued before any math (MLP=4) — the R7
// version ran at issue 7.4% / MLP 2, pure latency-bound.
// ---------------------------------------------------------------------------
__global__ void __launch_bounds__(256)
ldl_final_kernel(const float4* __restrict__ x,
                 const float* __restrict__ slw,
                 float4* __restrict__ out) {
    int i = blockIdx.x * blockDim.x + threadIdx.x;
    int j0 = i * 2;
    if (j0 >= N4) return;
    int j1 = j0 + 1;            // N4 = 400000 is even -> j1 always valid

    float s = 1.0f + __ldg(slw);
    float4 xv0 = x[j0];
    float4 xv1 = x[j1];
    float4 av0 = g_acc[j0];
    float4 av1 = g_acc[j1];

    float4 v0, v1;
    v0.x = fminf(fmaxf(fmaf(xv0.x, s, av0.x), 0.0f), 1.0f);
    v0.y = fminf(fmaxf(fmaf(xv0.y, s, av0.y), 0.0f), 1.0f);
    v0.z = fminf(fmaxf(fmaf(xv0.z, s, av0.z), 0.0f), 1.0f);
    v0.w = fminf(fmaxf(fmaf(xv0.w, s, av0.w), 0.0f), 1.0f);
    v1.x = fminf(fmaxf(fmaf(xv1.x, s, av1.x), 0.0f), 1.0f);
    v1.y = fminf(fmaxf(fmaf(xv1.y, s, av1.y), 0.0f), 1.0f);
    v1.z = fminf(fmaxf(fmaf(xv1.z, s, av1.z), 0.0f), 1.0f);
    v1.w = fminf(fmaxf(fmaf(xv1.w, s, av1.w), 0.0f), 1.0f);

    out[j0] = v0;
    out[j1] = v1;
    float4 z = make_float4(0.0f, 0.0f, 0.0f, 0.0f);
    g_acc[j0] = z;
    g_acc[j1] = z;
}

// ---------------------------------------------------------------------------
// Launch. Inputs (metadata order):
//   d_in[0] x                [N_NODES, 16] float32
//   d_in[1] edge_index       [2, E]        int64 OR int32 (runtime-detected)
//   d_in[2] edge_probs       [E]           float32
//   d_in[3] weight           [16]          float32
//   d_in[4] self_loop_weight scalar        float32
// Graph: [scatter -> finalize]; accumulator scratch keeps init off the
// critical path.
// ---------------------------------------------------------------------------
extern "C" void kernel_launch(void* const* d_in, const int* in_sizes, int n_in,
                              void* d_out, int out_size) {
    const float4* x     = (const float4*)d_in[0];
    const void*   eidx  = d_in[1];
    const float*  probs = (const float*)d_in[2];
    const float*  w     = (const float*)d_in[3];
    const float*  slw   = (const float*)d_in[4];
    float*        out   = (float*)d_out;

    const int E = in_sizes[2];   // edge_probs element count
    const int T = 256;

    long long n = 4LL * E;
    int gScat = (int)((n + T - 1) / T);
    ldl_scatter_kernel<<<gScat, T>>>(x, eidx, probs, w, E);

    int gFin = (N4 / 2 + T - 1) / T;
    ldl_final_kernel<<<gFin, T>>>(x, slw, (float4*)out);
}

// round 12
// speedup vs baseline: 1.0556x; 1.0222x over previous
#include <cuda_runtime.h>
#include <cstdint>

#define N_NODES 100000
#define DIM 16
#define NF   (N_NODES * DIM)       // total floats in node matrix
#define N4   (NF / 4)              // float4 count

// Edge-message accumulator. Zero-initialized at module load; the finalize
// kernel re-zeros it every call, so each graph replay starts from zero.
__device__ float4 g_acc[N4];

// ---------------------------------------------------------------------------
// Kernel 1: scatter — measured-best configuration (R7: 54.8us).
// 4 threads per edge (thread = one 16B chunk of the row). Per-block dtype
// detect: threads 0..63 read the first 64 8-byte words of edge_index; if the
// buffer is int32, the high words are random node ids -> almost surely
// outside [0, N_NODES); all-in-range <=> int64. One __syncthreads per block
// (T=256; per-warp variant measured worse in R9, T=512 worse in R9/R10).
// Lanes 4k..4k+3 read consecutive 16B of x[src] -> a warp's gather touches 8
// random rows instead of 32. One red.global.add.v4.f32 per thread (no-return
// 128b L2 reduction). Sits on the REDG per-lane issue floor (~55us for
// 12.8M lane-ops) — algorithmically minimal for this op.
// ---------------------------------------------------------------------------
__global__ void __launch_bounds__(256)
ldl_scatter_kernel(const float4* __restrict__ x,
                   const void* __restrict__ eidx,
                   const float* __restrict__ probs,
                   const float* __restrict__ weight,
                   int E) {
    __shared__ int s_ok[2];
    {
        int tid = threadIdx.x;
        if (tid < 64) {
            long long v = ((const long long*)eidx)[tid];
            bool ok = (v >= 0 && v < N_NODES);
            unsigned b = __ballot_sync(0xFFFFFFFFu, ok);
            if ((tid & 31) == 0) s_ok[tid >> 5] = (b == 0xFFFFFFFFu);
        }
        __syncthreads();
    }
    bool is64 = (s_ok[0] && s_ok[1]);

    int t = blockIdx.x * blockDim.x + threadIdx.x;
    int e = t >> 2;
    int c = t & 3;
    if (e >= E) return;

    long long s, d;
    if (is64) {
        const long long* p = (const long long*)eidx;
        s = __ldg(p + e);
        d = __ldg(p + E + e);
    } else {
        const int* p = (const int*)eidx;
        s = __ldg(p + e);
        d = __ldg(p + E + e);
    }
    if (s < 0 || s >= N_NODES || d < 0 || d >= N_NODES) return;  // backstop

    float pr = __ldg(probs + e);
    float4 wv = __ldg((const float4*)weight + c);   // warp-broadcast L1 hit
    float4 xv = __ldg(x + s * 4 + c);

    float a0 = xv.x * pr * wv.x;
    float a1 = xv.y * pr * wv.y;
    float a2 = xv.z * pr * wv.z;
    float a3 = xv.w * pr * wv.w;
    float* op = (float*)g_acc + d * DIM + c * 4;
    asm volatile(
        "red.global.add.v4.f32 [%0], {%1, %2, %3, %4};"
        :: "l"(op), "f"(a0), "f"(a1), "f"(a2), "f"(a3)
        : "memory");
}

// ---------------------------------------------------------------------------
// Kernel 2: finalize — measured-best configuration (R7: 6.6us).
// out = clip(x*(1+slw) + acc, 0, 1), and re-zero acc so the next graph
// replay starts clean. 1 float4/thread, 1563 blocks: max parallelism wins
// over per-thread MLP for this latency-bound stream (R10 coarsening: 8.0us).
// ---------------------------------------------------------------------------
__global__ void __launch_bounds__(256)
ldl_final_kernel(const float4* __restrict__ x,
                 const float* __restrict__ slw,
                 float4* __restrict__ out) {
    int i = blockIdx.x * blockDim.x + threadIdx.x;
    if (i < N4) {
        float s = 1.0f + __ldg(slw);
        float4 xv = x[i];
        float4 av = g_acc[i];
        float4 v;
        v.x = fminf(fmaxf(fmaf(xv.x, s, av.x), 0.0f), 1.0f);
        v.y = fminf(fmaxf(fmaf(xv.y, s, av.y), 0.0f), 1.0f);
        v.z = fminf(fmaxf(fmaf(xv.z, s, av.z), 0.0f), 1.0f);
        v.w = fminf(fmaxf(fmaf(xv.w, s, av.w), 0.0f), 1.0f);
        out[i] = v;
        g_acc[i] = make_float4(0.0f, 0.0f, 0.0f, 0.0f);
    }
}

// ---------------------------------------------------------------------------
// Launch. Inputs (metadata order):
//   d_in[0] x                [N_NODES, 16] float32
//   d_in[1] edge_index       [2, E]        int64 OR int32 (runtime-detected)
//   d_in[2] edge_probs       [E]           float32
//   d_in[3] weight           [16]          float32
//   d_in[4] self_loop_weight scalar        float32
// Graph: [scatter -> finalize]; accumulator scratch keeps init off the
// critical path.
// ---------------------------------------------------------------------------
extern "C" void kernel_launch(void* const* d_in, const int* in_sizes, int n_in,
                              void* d_out, int out_size) {
    const float4* x     = (const float4*)d_in[0];
    const void*   eidx  = d_in[1];
    const float*  probs = (const float*)d_in[2];
    const float*  w     = (const float*)d_in[3];
    const float*  slw   = (const float*)d_in[4];
    float*        out   = (float*)d_out;

    const int E = in_sizes[2];   // edge_probs element count
    const int T = 256;

    long long n = 4LL * E;
    int gScat = (int)((n + T - 1) / T);
    ldl_scatter_kernel<<<gScat, T>>>(x, eidx, probs, w, E);

    int gFin = (N4 + T - 1) / T;
    ldl_final_kernel<<<gFin, T>>>(x, slw, (float4*)out);
}

// round 13
// speedup vs baseline: 1.0666x; 1.0104x over previous
#include <cuda_runtime.h>
#include <cstdint>

#define N_NODES 100000
#define DIM 16
#define NF   (N_NODES * DIM)       // total floats in node matrix
#define N4   (NF / 4)              // float4 count

// Edge-message accumulator (holds sum of x[src]*prob, WITHOUT the weight
// factor — weight commutes with the segment-sum and is applied in finalize).
// Zero-initialized at module load; finalize re-zeros it every call.
__device__ float4 g_acc[N4];

// ---------------------------------------------------------------------------
// Kernel 1: scatter — measured-best configuration (R7 shape) minus the
// weight load/multiply (moved to finalize; weight is linear per-feature so
//   sum_e x[src]*p*w == w * sum_e x[src]*p ).
// 4 threads per edge (thread = one 16B chunk of the row). Per-block dtype
// detect: threads 0..63 read the first 64 8-byte words of edge_index; if the
// buffer is int32, the high words are random node ids -> almost surely
// outside [0, N_NODES); all-in-range <=> int64.
// Lanes 4k..4k+3 read consecutive 16B of x[src] -> a warp's gather touches 8
// random rows instead of 32. One red.global.add.v4.f32 per thread (no-return
// 128b L2 reduction). Sits on the REDG per-lane issue floor.
// ---------------------------------------------------------------------------
__global__ void __launch_bounds__(256)
ldl_scatter_kernel(const float4* __restrict__ x,
                   const void* __restrict__ eidx,
                   const float* __restrict__ probs,
                   int E) {
    __shared__ int s_ok[2];
    {
        int tid = threadIdx.x;
        if (tid < 64) {
            long long v = ((const long long*)eidx)[tid];
            bool ok = (v >= 0 && v < N_NODES);
            unsigned b = __ballot_sync(0xFFFFFFFFu, ok);
            if ((tid & 31) == 0) s_ok[tid >> 5] = (b == 0xFFFFFFFFu);
        }
        __syncthreads();
    }
    bool is64 = (s_ok[0] && s_ok[1]);

    int t = blockIdx.x * blockDim.x + threadIdx.x;
    int e = t >> 2;
    int c = t & 3;
    if (e >= E) return;

    long long s, d;
    if (is64) {
        const long long* p = (const long long*)eidx;
        s = __ldg(p + e);
        d = __ldg(p + E + e);
    } else {
        const int* p = (const int*)eidx;
        s = __ldg(p + e);
        d = __ldg(p + E + e);
    }
    if (s < 0 || s >= N_NODES || d < 0 || d >= N_NODES) return;  // backstop

    float pr = __ldg(probs + e);
    float4 xv = __ldg(x + s * 4 + c);

    float a0 = xv.x * pr;
    float a1 = xv.y * pr;
    float a2 = xv.z * pr;
    float a3 = xv.w * pr;
    float* op = (float*)g_acc + d * DIM + c * 4;
    asm volatile(
        "red.global.add.v4.f32 [%0], {%1, %2, %3, %4};"
        :: "l"(op), "f"(a0), "f"(a1), "f"(a2), "f"(a3)
        : "memory");
}

// ---------------------------------------------------------------------------
// Kernel 2: finalize — out = clip(x*(1+slw) + acc*weight, 0, 1), re-zero
// acc for the next replay. 1 float4/thread, 1563 blocks (measured best:
// max parallelism beats per-thread MLP for this latency-bound stream).
// The weight load is a warp-broadcast L1 hit (i & 3 selects the feature
// chunk); 4 extra FMULs are free at issue 8%.
// ---------------------------------------------------------------------------
__global__ void __launch_bounds__(256)
ldl_final_kernel(const float4* __restrict__ x,
                 const float* __restrict__ weight,
                 const float* __restrict__ slw,
                 float4* __restrict__ out) {
    int i = blockIdx.x * blockDim.x + threadIdx.x;
    if (i < N4) {
        float s = 1.0f + __ldg(slw);
        float4 wv = __ldg((const float4*)weight + (i & 3));
        float4 xv = x[i];
        float4 av = g_acc[i];
        float4 v;
        v.x = fminf(fmaxf(fmaf(av.x, wv.x, xv.x * s), 0.0f), 1.0f);
        v.y = fminf(fmaxf(fmaf(av.y, wv.y, xv.y * s), 0.0f), 1.0f);
        v.z = fminf(fmaxf(fmaf(av.z, wv.z, xv.z * s), 0.0f), 1.0f);
        v.w = fminf(fmaxf(fmaf(av.w, wv.w, xv.w * s), 0.0f), 1.0f);
        out[i] = v;
        g_acc[i] = make_float4(0.0f, 0.0f, 0.0f, 0.0f);
    }
}

// ---------------------------------------------------------------------------
// Launch. Inputs (metadata order):
//   d_in[0] x                [N_NODES, 16] float32
//   d_in[1] edge_index       [2, E]        int64 OR int32 (runtime-detected)
//   d_in[2] edge_probs       [E]           float32
//   d_in[3] weight           [16]          float32
//   d_in[4] self_loop_weight scalar        float32
// Graph: [scatter -> finalize]; accumulator scratch keeps init off the
// critical path; weight applied post-sum (linearity).
// ---------------------------------------------------------------------------
extern "C" void kernel_launch(void* const* d_in, const int* in_sizes, int n_in,
                              void* d_out, int out_size) {
    const float4* x     = (const float4*)d_in[0];
    const void*   eidx  = d_in[1];
    const float*  probs = (const float*)d_in[2];
    const float*  w     = (const float*)d_in[3];
    const float*  slw   = (const float*)d_in[4];
    float*        out   = (float*)d_out;

    const int E = in_sizes[2];   // edge_probs element count
    const int T = 256;

    long long n = 4LL * E;
    int gScat = (int)((n + T - 1) / T);
    ldl_scatter_kernel<<<gScat, T>>>(x, eidx, probs, E);

    int gFin = (N4 + T - 1) / T;
    ldl_final_kernel<<<gFin, T>>>(x, w, slw, (float4*)out);
}